// round 10
// baseline (speedup 1.0000x reference)
#include <cuda_runtime.h>
#include <math.h>

#define EPSF 1e-6f
#define THREADS 256
#define BLOCKS_PER_SM 6
#define NUM_SMS 148
#define MAX_BLOCKS 8192

static __device__ float g_partial[MAX_BLOCKS];
static __device__ unsigned int g_done;   // zero-init; reset in-kernel each run

// minimax atan on [0,1], extended via atan(x) = pi/2 - atan(1/x).
__device__ __forceinline__ float fast_atan_pos(float x)
{
    bool inv = x > 1.0f;
    float t = inv ? __fdividef(1.0f, x) : x;
    float t2 = t * t;
    float p = fmaf(t2, 0.0208351f, -0.0851330f);
    p = fmaf(t2, p, 0.1801410f);
    p = fmaf(t2, p, -0.3302995f);
    p = fmaf(t2, p, 0.9998660f);
    float r = t * p;
    return inv ? (1.5707963267948966f - r) : r;
}

// Liang–Barsky window with analytically-resolved entry/exit:
// a = u0/du (signed), ha = hu*|1/du| >= 0  ->  lo = -ha-a, hi = ha-a.
// Returns clamped window length dt (0 if empty); s = t0+t1 via out-param.
__device__ __forceinline__ float clip_core(
    float aU, float haU, float aV, float haV, float& s)
{
    float t0 = fmaxf(fmaxf(-haU - aU, -haV - aV), 0.0f);
    float t1 = fminf(fminf( haU - aU,  haV - aV), 1.0f);
    s = t0 + t1;
    return fmaxf(t1 - t0, 0.0f);
}

__device__ __forceinline__ float ciou_one(
    float px, float py, float pw, float ph, float pa,
    float qx, float qy, float qw, float qh, float qa)
{
    float ox = qx - px, oy = qy - py;

    float cp, sp, cq, sq;
    __sincosf(pa, &sp, &cp);
    __sincosf(qa, &sq, &cq);
    float hw1 = 0.5f * pw, hh1 = 0.5f * ph;
    float hw2 = 0.5f * qw, hh2 = 0.5f * qh;

    // relative rotation r = pa - qa
    float cr = fmaf(cp, cq,  sp * sq);
    float sr = fmaf(sp, cq, -cp * sq);

    // frame offsets
    float eu = fmaf(ox, cp,  oy * sp);       // box2 center in box1 frame
    float ev = fmaf(-ox, sp, oy * cp);
    float du_ = -fmaf(ox, cq,  oy * sq);     // box1 center in box2 frame
    float dv_ =  fmaf(ox, sq, -oy * cq);

    // half-extent projections
    float E = cr * hw2, F = sr * hh2, G = sr * hw2, H = cr * hh2;
    float A = cr * hw1, B = sr * hh1, C = sr * hw1, D = cr * hh1;

    // signed reciprocals of edge deltas (antiparallel edges share them)
    float E2 = E + E, F2 = F + F, G2 = G + G, H2 = H + H;
    float rE = __fdividef(1.0f, E2);
    float rF = __fdividef(1.0f, F2);
    float rG = __fdividef(1.0f, G2);
    float rH = __fdividef(1.0f, H2);
    float rB = __fdividef(1.0f, B + B);
    float rD = __fdividef(1.0f, D + D);

    // positive clip half-bounds (|r| is a free operand modifier)
    float haE = hw1 * fabsf(rE), haF = hw1 * fabsf(rF);
    float hbG = hh1 * fabsf(rG), hbH = hh1 * fabsf(rH);
    float hwB = hw2 * fabsf(rB), hhD = hh2 * fabsf(rD);

    // box2 corners in box1's frame (CCW), via shared partial sums
    float EpF = E + F, EmF = E - F, GpH = G + H, HmG = H - G;
    float tu0 = eu + EpF, tu1 = eu - EmF, tu2 = eu - EpF, tu3 = eu + EmF;
    float tv0 = ev + HmG, tv1 = ev + GpH, tv2 = ev - HmG, tv3 = ev - GpH;

    // box1 corners 1 and 3 in box2's frame (starts of its vertical edges)
    float ApB = A + B, DmC = D - C;
    float su1 = du_ - ApB, sv1 = dv_ + DmC;
    float su3 = du_ + ApB, sv3 = dv_ - DmC;

    // Green's theorem in box1's frame. box2 edges:
    // e0 d=(-2E, 2G)  e1 d=(-2F,-2H)  e2 d=(2E,-2G)  e3 d=(2F, 2H)
    float s, dt, area = 0.0f;

    dt = clip_core(-tu0 * rE, haE,  tv0 * rG, hbG, s);
    area = fmaf(G2 * dt, fmaf(-E, s, tu0), area);

    dt = clip_core(-tu1 * rF, haF, -tv1 * rH, hbH, s);
    area = fmaf(-(H2 * dt), fmaf(-F, s, tu1), area);

    dt = clip_core( tu2 * rE, haE, -tv2 * rG, hbG, s);
    area = fmaf(-(G2 * dt), fmaf(E, s, tu2), area);

    dt = clip_core( tu3 * rF, haF,  tv3 * rH, hbH, s);
    area = fmaf(H2 * dt, fmaf(F, s, tu3), area);

    // box1's vertical edges: e12 d=(2B,-2D) from corner1; e30 d=(-2B,2D) from corner3
    float dtv = clip_core( su1 * rB, hwB, -sv1 * rD, hhD, s)
              + clip_core(-su3 * rB, hwB,  sv3 * rD, hhD, s);
    float a1 = pw * ph;
    area = fmaf(0.5f * a1, dtv, area);       // 2*hw1*hh1 = 0.5*a1

    float inter = fabsf(area);

    // CIoU loss
    float a2 = qw * qh;
    float ious = fmaxf(__fdividef(inter, a1 + a2 - inter), EPSF);
    float cd = fmaf(ox, ox, oy * oy);

    float phe = ph + EPSF, qhe = qh + EPSF;
    float num = fmaf(qw, phe, -pw * qhe);
    float den = fmaf(qhe, phe, qw * pw);
    float da = fast_atan_pos(fabsf(__fdividef(num, den)));
    float aspect = 0.40528473456935109f * da * da;   // 4/pi^2

    // alpha*vterm = aspect^2 / (t*(omi*t + aspect)), t = omi + aspect
    float omi = 1.0f - ious;
    float t = omi + aspect;
    float av = __fdividef(aspect * aspect, t * fmaf(omi, t, aspect));
    return omi + __fdividef(cd, fmaf(pw, pw, ph * ph) + EPSF) + av;
}

__global__ void __launch_bounds__(THREADS, BLOCKS_PER_SM)
k_ciou(const float* __restrict__ pred,
       const float* __restrict__ target,
       const float* __restrict__ weight,
       float* __restrict__ out,
       int N, int npairs)
{
    int stride = gridDim.x * THREADS;
    float contrib = 0.0f;

    for (int p = blockIdx.x * THREADS + threadIdx.x; p < npairs; p += stride) {
        int i0 = 2 * p;
        if (i0 + 1 < N) {
            // vector path: 5x LDG.64 per array (offset 40p bytes, 8-aligned)
            const float2* P2 = (const float2*)(pred   + (size_t)p * 10);
            const float2* T2 = (const float2*)(target + (size_t)p * 10);
            float2 pr0 = P2[0], pr1 = P2[1], pr2 = P2[2], pr3 = P2[3], pr4 = P2[4];
            float2 tr0 = T2[0], tr1 = T2[1], tr2 = T2[2], tr3 = T2[3], tr4 = T2[4];
            float2 w2 = ((const float2*)weight)[p];

            float l0 = ciou_one(pr0.x, pr0.y, pr1.x, pr1.y, pr2.x,
                                tr0.x, tr0.y, tr1.x, tr1.y, tr2.x);
            float l1 = ciou_one(pr2.y, pr3.x, pr3.y, pr4.x, pr4.y,
                                tr2.y, tr3.x, tr3.y, tr4.x, tr4.y);
            contrib += fmaf(l0, w2.x, l1 * w2.y);
        } else {
            // tail: single box, scalar loads
            const float* P = pred   + (size_t)i0 * 5;
            const float* T = target + (size_t)i0 * 5;
            contrib += ciou_one(P[0], P[1], P[2], P[3], P[4],
                                T[0], T[1], T[2], T[3], T[4]) * weight[i0];
        }
    }

    // ---- block reduction ----
    #pragma unroll
    for (int o = 16; o > 0; o >>= 1)
        contrib += __shfl_down_sync(0xffffffffu, contrib, o);

    __shared__ float ws[THREADS / 32];
    __shared__ bool is_last;
    int lane = threadIdx.x & 31;
    int wid  = threadIdx.x >> 5;
    if (lane == 0) ws[wid] = contrib;
    __syncthreads();
    if (wid == 0) {
        float s = (lane < THREADS / 32) ? ws[lane] : 0.0f;
        #pragma unroll
        for (int o = 4; o > 0; o >>= 1)
            s += __shfl_down_sync(0xffu, s, o);
        if (lane == 0) {
            g_partial[blockIdx.x] = s;
            __threadfence();
            unsigned int t = atomicAdd(&g_done, 1u);
            is_last = (t == gridDim.x - 1);
        }
    }
    __syncthreads();

    // ---- last block: reduce partials, write mean, reset counter ----
    if (is_last) {
        int nblocks = gridDim.x;
        double acc = 0.0;
        for (int k = threadIdx.x; k < nblocks; k += THREADS)
            acc += (double)g_partial[k];

        #pragma unroll
        for (int o = 16; o > 0; o >>= 1)
            acc += __shfl_down_sync(0xffffffffu, acc, o);

        __shared__ double wd[THREADS / 32];
        if (lane == 0) wd[wid] = acc;
        __syncthreads();
        if (wid == 0) {
            double s = (lane < THREADS / 32) ? wd[lane] : 0.0;
            #pragma unroll
            for (int o = 4; o > 0; o >>= 1)
                s += __shfl_down_sync(0xffu, s, o);
            if (lane == 0) {
                out[0] = (float)(s / (double)N);
                g_done = 0;
            }
        }
    }
}

extern "C" void kernel_launch(void* const* d_in, const int* in_sizes, int n_in,
                              void* d_out, int out_size)
{
    const float* pred   = (const float*)d_in[0];
    const float* target = (const float*)d_in[1];
    const float* weight = (const float*)d_in[2];
    int N = in_sizes[2];

    int npairs = (N + 1) >> 1;
    int needed = (npairs + THREADS - 1) / THREADS;
    int blocks = NUM_SMS * BLOCKS_PER_SM;           // exactly one wave
    if (blocks > needed) blocks = needed;
    k_ciou<<<blocks, THREADS>>>(pred, target, weight, (float*)d_out, N, npairs);
}

// round 11
// speedup vs baseline: 1.1385x; 1.1385x over previous
#include <cuda_runtime.h>
#include <math.h>

#define EPSF 1e-6f
#define THREADS 256
#define MAX_BLOCKS 8192

static __device__ float g_partial[MAX_BLOCKS];
static __device__ unsigned int g_done;   // zero-init; reset in-kernel each run

// minimax atan on [0,1], extended via atan(x) = pi/2 - atan(1/x).
__device__ __forceinline__ float fast_atan_pos(float x)
{
    bool inv = x > 1.0f;
    float t = inv ? __fdividef(1.0f, x) : x;
    float t2 = t * t;
    float p = fmaf(t2, 0.0208351f, -0.0851330f);
    p = fmaf(t2, p, 0.1801410f);
    p = fmaf(t2, p, -0.3302995f);
    p = fmaf(t2, p, 0.9998660f);
    float r = t * p;
    return inv ? (1.5707963267948966f - r) : r;
}

// Liang–Barsky window with analytically-resolved entry/exit:
// a = u0/du (signed), ha = hu*|1/du| >= 0  ->  lo = -ha-a, hi = ha-a.
// Returns clamped window length dt (0 if empty); s = t0+t1 via out-param.
__device__ __forceinline__ float clip_core(
    float aU, float haU, float aV, float haV, float& s)
{
    float t0 = fmaxf(fmaxf(-haU - aU, -haV - aV), 0.0f);
    float t1 = fminf(fminf( haU - aU,  haV - aV), 1.0f);
    s = t0 + t1;
    return fmaxf(t1 - t0, 0.0f);
}

__device__ __forceinline__ float ciou_one(
    float px, float py, float pw, float ph, float pa,
    float qx, float qy, float qw, float qh, float qa)
{
    float ox = qx - px, oy = qy - py;

    float cp, sp, cq, sq;
    __sincosf(pa, &sp, &cp);
    __sincosf(qa, &sq, &cq);
    float hw1 = 0.5f * pw, hh1 = 0.5f * ph;
    float hw2 = 0.5f * qw, hh2 = 0.5f * qh;

    // relative rotation r = pa - qa
    float cr = fmaf(cp, cq,  sp * sq);
    float sr = fmaf(sp, cq, -cp * sq);

    // frame offsets
    float eu = fmaf(ox, cp,  oy * sp);       // box2 center in box1 frame
    float ev = fmaf(-ox, sp, oy * cp);
    float du_ = -fmaf(ox, cq,  oy * sq);     // box1 center in box2 frame
    float dv_ =  fmaf(ox, sq, -oy * cq);

    // half-extent projections
    float E = cr * hw2, F = sr * hh2, G = sr * hw2, H = cr * hh2;
    float A = cr * hw1, B = sr * hh1, C = sr * hw1, D = cr * hh1;

    // signed reciprocals of edge deltas (antiparallel edges share them)
    float E2 = E + E, F2 = F + F, G2 = G + G, H2 = H + H;
    float rE = __fdividef(1.0f, E2);
    float rF = __fdividef(1.0f, F2);
    float rG = __fdividef(1.0f, G2);
    float rH = __fdividef(1.0f, H2);
    float rB = __fdividef(1.0f, B + B);
    float rD = __fdividef(1.0f, D + D);

    // positive clip half-bounds (|r| is a free operand modifier)
    float haE = hw1 * fabsf(rE), haF = hw1 * fabsf(rF);
    float hbG = hh1 * fabsf(rG), hbH = hh1 * fabsf(rH);
    float hwB = hw2 * fabsf(rB), hhD = hh2 * fabsf(rD);

    // box2 corners in box1's frame (CCW), via shared partial sums
    float EpF = E + F, EmF = E - F, GpH = G + H, HmG = H - G;
    float tu0 = eu + EpF, tu1 = eu - EmF, tu2 = eu - EpF, tu3 = eu + EmF;
    float tv0 = ev + HmG, tv1 = ev + GpH, tv2 = ev - HmG, tv3 = ev - GpH;

    // box1 corners 1 and 3 in box2's frame (starts of its vertical edges)
    float ApB = A + B, DmC = D - C;
    float su1 = du_ - ApB, sv1 = dv_ + DmC;
    float su3 = du_ + ApB, sv3 = dv_ - DmC;

    // Green's theorem in box1's frame. box2 edges:
    // e0 d=(-2E, 2G)  e1 d=(-2F,-2H)  e2 d=(2E,-2G)  e3 d=(2F, 2H)
    float s, dt, area = 0.0f;

    dt = clip_core(-tu0 * rE, haE,  tv0 * rG, hbG, s);
    area = fmaf(G2 * dt, fmaf(-E, s, tu0), area);

    dt = clip_core(-tu1 * rF, haF, -tv1 * rH, hbH, s);
    area = fmaf(-(H2 * dt), fmaf(-F, s, tu1), area);

    dt = clip_core( tu2 * rE, haE, -tv2 * rG, hbG, s);
    area = fmaf(-(G2 * dt), fmaf(E, s, tu2), area);

    dt = clip_core( tu3 * rF, haF,  tv3 * rH, hbH, s);
    area = fmaf(H2 * dt, fmaf(F, s, tu3), area);

    // box1's vertical edges: e12 d=(2B,-2D) from corner1; e30 d=(-2B,2D) from corner3
    float dtv = clip_core( su1 * rB, hwB, -sv1 * rD, hhD, s)
              + clip_core(-su3 * rB, hwB,  sv3 * rD, hhD, s);
    float a1 = pw * ph;
    area = fmaf(0.5f * a1, dtv, area);       // 2*hw1*hh1 = 0.5*a1

    float inter = fabsf(area);

    // CIoU loss
    float a2 = qw * qh;
    float ious = fmaxf(__fdividef(inter, a1 + a2 - inter), EPSF);
    float cd = fmaf(ox, ox, oy * oy);

    float phe = ph + EPSF, qhe = qh + EPSF;
    float num = fmaf(qw, phe, -pw * qhe);
    float den = fmaf(qhe, phe, qw * pw);
    float da = fast_atan_pos(fabsf(__fdividef(num, den)));
    float aspect = 0.40528473456935109f * da * da;   // 4/pi^2

    // alpha*vterm = aspect^2 / (t*(omi*t + aspect)), t = omi + aspect
    float omi = 1.0f - ious;
    float t = omi + aspect;
    float av = __fdividef(aspect * aspect, t * fmaf(omi, t, aspect));
    return omi + __fdividef(cd, fmaf(pw, pw, ph * ph) + EPSF) + av;
}

__global__ void __launch_bounds__(THREADS, 6) k_ciou(const float* __restrict__ pred,
                                                     const float* __restrict__ target,
                                                     const float* __restrict__ weight,
                                                     float* __restrict__ out,
                                                     int N)
{
    int p = blockIdx.x * THREADS + threadIdx.x;   // pair index
    int i0 = 2 * p;
    float contrib = 0.0f;

    if (i0 + 1 < N) {
        // vector path: 5x LDG.64 per array (offset 40p bytes, 8-aligned)
        const float2* P2 = (const float2*)(pred   + (size_t)p * 10);
        const float2* T2 = (const float2*)(target + (size_t)p * 10);
        float2 pr0 = P2[0], pr1 = P2[1], pr2 = P2[2], pr3 = P2[3], pr4 = P2[4];
        float2 tr0 = T2[0], tr1 = T2[1], tr2 = T2[2], tr3 = T2[3], tr4 = T2[4];
        float2 w2 = ((const float2*)weight)[p];

        float l0 = ciou_one(pr0.x, pr0.y, pr1.x, pr1.y, pr2.x,
                            tr0.x, tr0.y, tr1.x, tr1.y, tr2.x);
        float l1 = ciou_one(pr2.y, pr3.x, pr3.y, pr4.x, pr4.y,
                            tr2.y, tr3.x, tr3.y, tr4.x, tr4.y);
        contrib = fmaf(l0, w2.x, l1 * w2.y);
    } else if (i0 < N) {
        // tail: single box, scalar loads
        const float* P = pred   + (size_t)i0 * 5;
        const float* T = target + (size_t)i0 * 5;
        contrib = ciou_one(P[0], P[1], P[2], P[3], P[4],
                           T[0], T[1], T[2], T[3], T[4]) * weight[i0];
    }

    // ---- block reduction ----
    #pragma unroll
    for (int o = 16; o > 0; o >>= 1)
        contrib += __shfl_down_sync(0xffffffffu, contrib, o);

    __shared__ float ws[THREADS / 32];
    __shared__ bool is_last;
    int lane = threadIdx.x & 31;
    int wid  = threadIdx.x >> 5;
    if (lane == 0) ws[wid] = contrib;
    __syncthreads();
    if (wid == 0) {
        float s = (lane < THREADS / 32) ? ws[lane] : 0.0f;
        #pragma unroll
        for (int o = 4; o > 0; o >>= 1)
            s += __shfl_down_sync(0xffu, s, o);
        if (lane == 0) {
            g_partial[blockIdx.x] = s;
            __threadfence();
            unsigned int t = atomicAdd(&g_done, 1u);
            is_last = (t == gridDim.x - 1);
        }
    }
    __syncthreads();

    // ---- last block: reduce partials, write mean, reset counter ----
    if (is_last) {
        int nblocks = gridDim.x;
        double acc = 0.0;
        for (int k = threadIdx.x; k < nblocks; k += THREADS)
            acc += (double)g_partial[k];

        #pragma unroll
        for (int o = 16; o > 0; o >>= 1)
            acc += __shfl_down_sync(0xffffffffu, acc, o);

        __shared__ double wd[THREADS / 32];
        if (lane == 0) wd[wid] = acc;
        __syncthreads();
        if (wid == 0) {
            double s = (lane < THREADS / 32) ? wd[lane] : 0.0;
            #pragma unroll
            for (int o = 4; o > 0; o >>= 1)
                s += __shfl_down_sync(0xffu, s, o);
            if (lane == 0) {
                out[0] = (float)(s / (double)N);
                g_done = 0;
            }
        }
    }
}

extern "C" void kernel_launch(void* const* d_in, const int* in_sizes, int n_in,
                              void* d_out, int out_size)
{
    const float* pred   = (const float*)d_in[0];
    const float* target = (const float*)d_in[1];
    const float* weight = (const float*)d_in[2];
    int N = in_sizes[2];

    int pairs = (N + 1) >> 1;
    int blocks = (pairs + THREADS - 1) / THREADS;
    k_ciou<<<blocks, THREADS>>>(pred, target, weight, (float*)d_out, N);
}